// round 3
// baseline (speedup 1.0000x reference)
#include <cuda_runtime.h>
#include <cstdint>

// Problem constants
#define C_IN   256
#define K_TOT  1280          // 5 * 256
#define KCH    16            // K chunk
#define NCHUNK (K_TOT / KCH) // 80
#define MT     128           // rows per block
#define NTHREADS 512

// ---- packed f32x2 helpers ------------------------------------------------
__device__ __forceinline__ unsigned long long pk2(float lo, float hi) {
    unsigned long long u;
    asm("mov.b64 %0, {%1, %2};" : "=l"(u) : "f"(lo), "f"(hi));
    return u;
}
__device__ __forceinline__ void upk2(unsigned long long u, float& lo, float& hi) {
    asm("mov.b64 {%0, %1}, %2;" : "=f"(lo), "=f"(hi) : "l"(u));
}
__device__ __forceinline__ void fma2(unsigned long long& d,
                                     unsigned long long a,
                                     unsigned long long b) {
    asm("fma.rn.f32x2 %0, %1, %2, %0;" : "+l"(d) : "l"(a), "l"(b));
}

__global__ void __launch_bounds__(NTHREADS, 1)
sparse_mesh_conv_kernel(const float* __restrict__ x,
                        const int* __restrict__ idx1,
                        const int* __restrict__ idx2,
                        const int* __restrict__ idx3,
                        const int* __restrict__ idx4,
                        const float* __restrict__ W,
                        const float* __restrict__ bias,
                        const float* __restrict__ gamma,
                        const float* __restrict__ beta,
                        float* __restrict__ out,
                        int nRows)
{
    __shared__ float sW[KCH][C_IN];     // 16 KB: W chunk (k-major rows)
    __shared__ float sP[KCH][MT];       //  8 KB: patch chunk, TRANSPOSED (k, row)
    __shared__ int   sIdx[4][MT];       //  2 KB: idx1..4 for this block's rows

    const int tid   = threadIdx.x;
    const int bRow0 = blockIdx.x * MT;

    // ---- load neighbor indices for this block's 128 rows ----
    {
        const int a = tid >> 7;          // which idx array (0..3)
        const int r = tid & 127;
        int rg = bRow0 + r;
        if (rg >= nRows) rg = nRows - 1;
        const int* ip = (a == 0) ? idx1 : (a == 1) ? idx2 : (a == 2) ? idx3 : idx4;
        sIdx[a][r] = ip[rg];
    }

    // ---- GEMM thread mapping: warp = 8 rows, lane = 8 cols ----
    const int tc = tid & 31;            // lane -> column group
    const int tr = tid >> 5;            // warp -> row group
    const int r0 = tr * 8;              // rows r0..r0+7 (block-local)
    const int c0 = tc * 8;              // cols c0..c0+7

    unsigned long long acc[8][4];
    #pragma unroll
    for (int i = 0; i < 8; i++)
        #pragma unroll
        for (int j = 0; j < 4; j++)
            acc[i][j] = 0ull;

    // ---- staging thread mapping for patch build ----
    const int prow = tid >> 2;          // 0..127
    const int sub  = tid & 3;           // 4 floats each -> 16 cols per chunk
    int prg = bRow0 + prow;
    if (prg >= nRows) prg = nRows - 1;

    // ---- staging mapping for W chunk ----
    const int wk = tid >> 5;            // 0..15 (chunk-local k)
    const int wc = (tid & 31) * 8;      // 0..248

    for (int kc = 0; kc < NCHUNK; ++kc) {
        __syncthreads();   // previous chunk's compute done (also orders sIdx on kc==0)

        // -- stage W[kc*16 .. +16, :] --
        {
            const float* wg = W + (size_t)(kc * KCH + wk) * C_IN + wc;
            const float4 w0 = *(const float4*)(wg);
            const float4 w1 = *(const float4*)(wg + 4);
            *(float4*)&sW[wk][wc]     = w0;
            *(float4*)&sW[wk][wc + 4] = w1;
        }

        // -- build patch chunk (transposed into sP[k][row]) --
        {
            const int kg   = kc * KCH;
            const int seg  = kg >> 8;              // 0..4 (chunk never crosses segments)
            const int ccol = (kg & 255) + sub * 4; // global channel of this float4
            float4 v;
            if (seg == 0) {
                v = *(const float4*)(x + (size_t)prg * C_IN + ccol);
            } else {
                int sA, sB;
                if (seg <= 2) { sA = sIdx[0][prow]; sB = sIdx[2][prow]; } // a = x[idx1], c = x[idx3]
                else          { sA = sIdx[1][prow]; sB = sIdx[3][prow]; } // b = x[idx2], d = x[idx4]
                const float4 va = *(const float4*)(x + (size_t)sA * C_IN + ccol);
                const float4 vb = *(const float4*)(x + (size_t)sB * C_IN + ccol);
                if (seg & 1) { // |a-c| or |b-d|
                    v.x = fabsf(va.x - vb.x); v.y = fabsf(va.y - vb.y);
                    v.z = fabsf(va.z - vb.z); v.w = fabsf(va.w - vb.w);
                } else {       // a+c or b+d
                    v.x = va.x + vb.x; v.y = va.y + vb.y;
                    v.z = va.z + vb.z; v.w = va.w + vb.w;
                }
            }
            const int kb = sub * 4;
            sP[kb + 0][prow] = v.x;
            sP[kb + 1][prow] = v.y;
            sP[kb + 2][prow] = v.z;
            sP[kb + 3][prow] = v.w;
        }

        __syncthreads();

        // -- compute: 16 k-steps, 8x8 micro-tile as f32x2 pairs --
        #pragma unroll
        for (int kk = 0; kk < KCH; ++kk) {
            const float4 pa = *(const float4*)&sP[kk][r0];     // broadcast across lanes
            const float4 pb = *(const float4*)&sP[kk][r0 + 4];
            const float4 wa = *(const float4*)&sW[kk][c0];
            const float4 wb = *(const float4*)&sW[kk][c0 + 4];
            unsigned long long w2[4] = { pk2(wa.x, wa.y), pk2(wa.z, wa.w),
                                         pk2(wb.x, wb.y), pk2(wb.z, wb.w) };
            const float p[8] = { pa.x, pa.y, pa.z, pa.w, pb.x, pb.y, pb.z, pb.w };
            #pragma unroll
            for (int i = 0; i < 8; i++) {
                const unsigned long long pd = pk2(p[i], p[i]);
                #pragma unroll
                for (int j = 0; j < 4; j++)
                    fma2(acc[i][j], pd, w2[j]);
            }
        }
    }

    // ---- epilogue: bias + LayerNorm + residual + exact GELU ----
    float bv[8], gv[8], bev[8];
    {
        const float4 b0 = *(const float4*)(bias  + c0);
        const float4 b1 = *(const float4*)(bias  + c0 + 4);
        const float4 g0 = *(const float4*)(gamma + c0);
        const float4 g1 = *(const float4*)(gamma + c0 + 4);
        const float4 e0 = *(const float4*)(beta  + c0);
        const float4 e1 = *(const float4*)(beta  + c0 + 4);
        bv[0]=b0.x; bv[1]=b0.y; bv[2]=b0.z; bv[3]=b0.w; bv[4]=b1.x; bv[5]=b1.y; bv[6]=b1.z; bv[7]=b1.w;
        gv[0]=g0.x; gv[1]=g0.y; gv[2]=g0.z; gv[3]=g0.w; gv[4]=g1.x; gv[5]=g1.y; gv[6]=g1.z; gv[7]=g1.w;
        bev[0]=e0.x; bev[1]=e0.y; bev[2]=e0.z; bev[3]=e0.w; bev[4]=e1.x; bev[5]=e1.y; bev[6]=e1.z; bev[7]=e1.w;
    }

    const float inv_c = 1.0f / (float)C_IN;
    #pragma unroll 1
    for (int i = 0; i < 8; i++) {
        const int rg = bRow0 + r0 + i;
        if (rg >= nRows) break;     // uniform across the warp (all lanes share rows)

        float y[8];
        #pragma unroll
        for (int j = 0; j < 4; j++)
            upk2(acc[i][j], y[2 * j], y[2 * j + 1]);
        #pragma unroll
        for (int j = 0; j < 8; j++) y[j] += bv[j];

        // mean over 256 channels: per-thread partial + lane reduction
        float s = 0.f;
        #pragma unroll
        for (int j = 0; j < 8; j++) s += y[j];
        #pragma unroll
        for (int o = 16; o > 0; o >>= 1) s += __shfl_xor_sync(0xffffffffu, s, o);
        const float mu = s * inv_c;

        float vs = 0.f;
        #pragma unroll
        for (int j = 0; j < 8; j++) { const float d = y[j] - mu; vs += d * d; }
        #pragma unroll
        for (int o = 16; o > 0; o >>= 1) vs += __shfl_xor_sync(0xffffffffu, vs, o);
        const float rstd = rsqrtf(vs * inv_c + 1e-5f);

        const float4 x0 = *(const float4*)(x + (size_t)rg * C_IN + c0);
        const float4 x1 = *(const float4*)(x + (size_t)rg * C_IN + c0 + 4);
        const float xr[8] = { x0.x, x0.y, x0.z, x0.w, x1.x, x1.y, x1.z, x1.w };

        float o8[8];
        #pragma unroll
        for (int j = 0; j < 8; j++) {
            const float t = (y[j] - mu) * rstd * gv[j] + bev[j] + xr[j];
            o8[j] = t * normcdff(t);        // exact (erf) GELU
        }
        float* op = out + (size_t)rg * C_IN + c0;
        *(float4*)(op)     = make_float4(o8[0], o8[1], o8[2], o8[3]);
        *(float4*)(op + 4) = make_float4(o8[4], o8[5], o8[6], o8[7]);
    }
}

extern "C" void kernel_launch(void* const* d_in, const int* in_sizes, int n_in,
                              void* d_out, int out_size)
{
    const float* x     = (const float*)d_in[0];
    const int*   idx1  = (const int*)d_in[1];
    const int*   idx2  = (const int*)d_in[2];
    const int*   idx3  = (const int*)d_in[3];
    const int*   idx4  = (const int*)d_in[4];
    const float* W     = (const float*)d_in[5];
    const float* bias  = (const float*)d_in[6];
    const float* gamma = (const float*)d_in[7];
    const float* beta  = (const float*)d_in[8];
    float* out = (float*)d_out;

    const int n = in_sizes[1];          // N (element count of idx1)
    const int grid = (n + MT - 1) / MT;

    sparse_mesh_conv_kernel<<<grid, NTHREADS>>>(
        x, idx1, idx2, idx3, idx4, W, bias, gamma, beta, out, n);
}

// round 5
// speedup vs baseline: 4.4104x; 4.4104x over previous
#include <cuda_runtime.h>
#include <cuda_fp16.h>
#include <cstdint>

#define C_OUT   256
#define C_IN    256
#define K_TOT   1280
#define KCH     64               // k per chunk (fp16) -> 128B per row
#define NCH     (K_TOT / KCH)    // 20
#define MT      128              // rows per CTA
#define NTHREADS 512             // 16 warps: 4x4 warp grid, warp tile 32x64

// dynamic smem layout (all rows are 128B, SW128-style swizzled)
#define SO_A    0                // [2][128*128]  A patch fp16      (2 x 16KB)
#define SO_BH   32768            // [2][256*128]  W hi fp16         (2 x 32KB)
#define SO_BL   98304            // [2][256*128]  W lo fp16         (2 x 32KB)
#define SMEM_BYTES 163840

// W split scratch: Wt[n][k] fp16 hi/lo
__device__ __half g_Wh[C_OUT * K_TOT];
__device__ __half g_Wl[C_OUT * K_TOT];

// ---------------- helpers ----------------
__device__ __forceinline__ uint32_t smem_u32(const void* p) {
    uint32_t a;
    asm("{ .reg .u64 t; cvta.to.shared.u64 t, %1; cvt.u32.u64 %0, t; }" : "=r"(a) : "l"(p));
    return a;
}
__device__ __forceinline__ uint32_t swz(uint32_t b) { return b ^ ((b >> 3) & 0x70); }

__device__ __forceinline__ void ldsm4(uint32_t* r, uint32_t a) {
    asm volatile("ldmatrix.sync.aligned.m8n8.x4.shared.b16 {%0,%1,%2,%3}, [%4];"
                 : "=r"(r[0]), "=r"(r[1]), "=r"(r[2]), "=r"(r[3]) : "r"(a));
}
__device__ __forceinline__ void mma16816(float* c, const uint32_t* a, const uint32_t* b) {
    asm volatile("mma.sync.aligned.m16n8k16.row.col.f32.f16.f16.f32 "
                 "{%0,%1,%2,%3}, {%4,%5,%6,%7}, {%8,%9}, {%0,%1,%2,%3};"
                 : "+f"(c[0]), "+f"(c[1]), "+f"(c[2]), "+f"(c[3])
                 : "r"(a[0]), "r"(a[1]), "r"(a[2]), "r"(a[3]), "r"(b[0]), "r"(b[1]));
}
__device__ __forceinline__ uint32_t pkh2(float a, float b) {
    __half2 h = __floats2half2_rn(a, b);
    return *reinterpret_cast<uint32_t*>(&h);
}

// ---------------- prep: W[k][n] fp32 -> Wt hi/lo fp16 [n][k] ----------------
__global__ void prep_w_kernel(const float* __restrict__ W) {
    const int n = blockIdx.x;
    for (int k = threadIdx.x; k < K_TOT; k += blockDim.x) {
        const float w = W[(size_t)k * C_OUT + n];
        const __half h = __float2half_rn(w);
        g_Wh[n * K_TOT + k] = h;
        g_Wl[n * K_TOT + k] = __float2half_rn(w - __half2float(h));
    }
}

// ---------------- staging: build A patch chunk + copy W chunk ----------------
__device__ __forceinline__ void stage_chunk(char* ds, int kc, int tid, int bRow0,
                                            int nRows, const float* __restrict__ x,
                                            const int (*sIdx)[MT])
{
    const int b = kc & 1;
    const int kg0 = kc * KCH;
    const int seg = kg0 >> 8;            // 0..4 (chunk never crosses segments)
    const int colbase = kg0 & 255;
    char* A  = ds + SO_A  + b * 16384;
    char* BH = ds + SO_BH + b * 32768;
    char* BL = ds + SO_BL + b * 32768;

    // A: 128 rows x 64 fp16; 1024 x 16B stores -> 2 iters of 512 threads
    #pragma unroll
    for (int it = 0; it < 2; ++it) {
        const int s = tid + it * NTHREADS;
        const int row = s >> 3;
        const int k8 = (s & 7) * 8;
        const int ccol = colbase + k8;
        float v[8];
        if (seg == 0) {
            int rg = bRow0 + row; if (rg >= nRows) rg = nRows - 1;
            const float4 v0 = *(const float4*)(x + (size_t)rg * C_IN + ccol);
            const float4 v1 = *(const float4*)(x + (size_t)rg * C_IN + ccol + 4);
            v[0]=v0.x; v[1]=v0.y; v[2]=v0.z; v[3]=v0.w;
            v[4]=v1.x; v[5]=v1.y; v[6]=v1.z; v[7]=v1.w;
        } else {
            int sA, sB;
            if (seg <= 2) { sA = sIdx[0][row]; sB = sIdx[2][row]; }   // a,c
            else          { sA = sIdx[1][row]; sB = sIdx[3][row]; }   // b,d
            const float4 a0 = *(const float4*)(x + (size_t)sA * C_IN + ccol);
            const float4 a1 = *(const float4*)(x + (size_t)sA * C_IN + ccol + 4);
            const float4 b0 = *(const float4*)(x + (size_t)sB * C_IN + ccol);
            const float4 b1 = *(const float4*)(x + (size_t)sB * C_IN + ccol + 4);
            if (seg & 1) {   // |a-c| or |b-d|
                v[0]=fabsf(a0.x-b0.x); v[1]=fabsf(a0.y-b0.y);
                v[2]=fabsf(a0.z-b0.z); v[3]=fabsf(a0.w-b0.w);
                v[4]=fabsf(a1.x-b1.x); v[5]=fabsf(a1.y-b1.y);
                v[6]=fabsf(a1.z-b1.z); v[7]=fabsf(a1.w-b1.w);
            } else {         // a+c or b+d
                v[0]=a0.x+b0.x; v[1]=a0.y+b0.y; v[2]=a0.z+b0.z; v[3]=a0.w+b0.w;
                v[4]=a1.x+b1.x; v[5]=a1.y+b1.y; v[6]=a1.z+b1.z; v[7]=a1.w+b1.w;
            }
        }
        uint4 w;
        w.x = pkh2(v[0], v[1]); w.y = pkh2(v[2], v[3]);
        w.z = pkh2(v[4], v[5]); w.w = pkh2(v[6], v[7]);
        *(uint4*)(A + swz(row * 128 + k8 * 2)) = w;
    }

    // B hi/lo: 256 rows x 64 fp16 each; 2048 x 16B -> 4 iters
    #pragma unroll
    for (int it = 0; it < 4; ++it) {
        const int s = tid + it * NTHREADS;
        const int n = s >> 3;
        const int k8 = (s & 7) * 8;
        const uint32_t sw = swz(n * 128 + k8 * 2);
        *(uint4*)(BH + sw) = *(const uint4*)(g_Wh + n * K_TOT + kg0 + k8);
        *(uint4*)(BL + sw) = *(const uint4*)(g_Wl + n * K_TOT + kg0 + k8);
    }
}

// ---------------- main kernel ----------------
__global__ void __launch_bounds__(NTHREADS, 1)
smc_mma_kernel(const float* __restrict__ x,
               const int* __restrict__ idx1, const int* __restrict__ idx2,
               const int* __restrict__ idx3, const int* __restrict__ idx4,
               const float* __restrict__ bias, const float* __restrict__ gamma,
               const float* __restrict__ beta,
               float* __restrict__ out, int nRows)
{
    extern __shared__ char ds[];
    __shared__ int    sIdx[4][MT];
    __shared__ float2 sPart[MT][4];

    const uint32_t sb = smem_u32(ds);
    const int tid  = threadIdx.x;
    const int lane = tid & 31;
    const int wid  = tid >> 5;
    const int wm   = wid & 3;     // warp row group (32 rows)
    const int wn   = wid >> 2;    // warp col group (64 cols)
    const int bRow0 = blockIdx.x * MT;

    // neighbor indices
    {
        const int a = tid >> 7, r = tid & 127;
        int rg = bRow0 + r; if (rg >= nRows) rg = nRows - 1;
        const int* ip = (a == 0) ? idx1 : (a == 1) ? idx2 : (a == 2) ? idx3 : idx4;
        sIdx[a][r] = ip[rg];
    }
    __syncthreads();

    float acc[2][8][4];
    #pragma unroll
    for (int i = 0; i < 2; i++)
        #pragma unroll
        for (int j = 0; j < 8; j++)
            #pragma unroll
            for (int e = 0; e < 4; e++) acc[i][j][e] = 0.f;

    // per-lane ldmatrix address components
    const int lA_row = wm * 32 + (lane & 7) + ((lane >> 3) & 1) * 8; // + mt*16
    const int lA_k8  = ((lane >> 4) & 1) * 8;
    const int lB_n   = wn * 64 + (lane & 7) + ((lane >> 4) & 1) * 8; // + ng*16
    const int lB_k8  = ((lane >> 3) & 1) * 8;

    stage_chunk(ds, 0, tid, bRow0, nRows, x, sIdx);
    __syncthreads();

    for (int kc = 0; kc < NCH; ++kc) {
        if (kc + 1 < NCH)
            stage_chunk(ds, kc + 1, tid, bRow0, nRows, x, sIdx);  // other buffer

        const uint32_t Ab  = sb + SO_A  + (kc & 1) * 16384;
        const uint32_t BHb = sb + SO_BH + (kc & 1) * 32768;
        const uint32_t BLb = sb + SO_BL + (kc & 1) * 32768;

        #pragma unroll
        for (int ks = 0; ks < 4; ++ks) {
            const int kb = ks * 16;
            uint32_t a0[4], a1[4];
            ldsm4(a0, Ab + swz((uint32_t)(lA_row       * 128 + (kb + lA_k8) * 2)));
            ldsm4(a1, Ab + swz((uint32_t)((lA_row + 16) * 128 + (kb + lA_k8) * 2)));
            #pragma unroll
            for (int ng = 0; ng < 4; ++ng) {
                const uint32_t boff = swz((uint32_t)((lB_n + ng * 16) * 128 + (kb + lB_k8) * 2));
                uint32_t bh[4], bl[4];
                ldsm4(bh, BHb + boff);
                ldsm4(bl, BLb + boff);
                mma16816(acc[0][2*ng+0], a0, bh + 0);
                mma16816(acc[0][2*ng+1], a0, bh + 2);
                mma16816(acc[1][2*ng+0], a1, bh + 0);
                mma16816(acc[1][2*ng+1], a1, bh + 2);
                mma16816(acc[0][2*ng+0], a0, bl + 0);
                mma16816(acc[0][2*ng+1], a0, bl + 2);
                mma16816(acc[1][2*ng+0], a1, bl + 0);
                mma16816(acc[1][2*ng+1], a1, bl + 2);
            }
        }
        __syncthreads();
    }

    // ---------------- epilogue: bias + LN + residual + exact GELU ----------------
    const int cbase = wn * 64 + (lane & 3) * 2;

    // fold bias into accumulators
    #pragma unroll
    for (int nt = 0; nt < 8; ++nt) {
        const float2 bv = *(const float2*)(bias + cbase + nt * 8);
        #pragma unroll
        for (int mt = 0; mt < 2; ++mt) {
            acc[mt][nt][0] += bv.x; acc[mt][nt][1] += bv.y;
            acc[mt][nt][2] += bv.x; acc[mt][nt][3] += bv.y;
        }
    }

    // per-row partial sums (this warp covers 64 cols)
    #pragma unroll
    for (int mt = 0; mt < 2; ++mt)
        #pragma unroll
        for (int h = 0; h < 2; ++h) {
            float s = 0.f, s2 = 0.f;
            #pragma unroll
            for (int nt = 0; nt < 8; ++nt) {
                const float y0 = acc[mt][nt][h*2], y1 = acc[mt][nt][h*2+1];
                s += y0 + y1; s2 += y0*y0 + y1*y1;
            }
            s  += __shfl_xor_sync(0xffffffffu, s, 1);
            s2 += __shfl_xor_sync(0xffffffffu, s2, 1);
            s  += __shfl_xor_sync(0xffffffffu, s, 2);
            s2 += __shfl_xor_sync(0xffffffffu, s2, 2);
            if ((lane & 3) == 0) {
                const int row = wm * 32 + mt * 16 + h * 8 + (lane >> 2);
                sPart[row][wn] = make_float2(s, s2);
            }
        }
    __syncthreads();

    float2 gv[8], ev[8];
    #pragma unroll
    for (int nt = 0; nt < 8; ++nt) {
        gv[nt] = *(const float2*)(gamma + cbase + nt * 8);
        ev[nt] = *(const float2*)(beta  + cbase + nt * 8);
    }

    #pragma unroll
    for (int mt = 0; mt < 2; ++mt)
        #pragma unroll
        for (int h = 0; h < 2; ++h) {
            const int row = wm * 32 + mt * 16 + h * 8 + (lane >> 2);
            const float2 p0 = sPart[row][0], p1 = sPart[row][1];
            const float2 p2 = sPart[row][2], p3 = sPart[row][3];
            const float S  = p0.x + p1.x + p2.x + p3.x;
            const float S2 = p0.y + p1.y + p2.y + p3.y;
            const float mu = S * (1.0f / 256.0f);
            const float var = S2 * (1.0f / 256.0f) - mu * mu;
            const float rstd = rsqrtf(var + 1e-5f);
            const int rg = bRow0 + row;
            if (rg < nRows) {
                #pragma unroll
                for (int nt = 0; nt < 8; ++nt) {
                    const float2 xv = *(const float2*)(x + (size_t)rg * C_IN + cbase + nt * 8);
                    const float t0 = (acc[mt][nt][h*2]   - mu) * rstd * gv[nt].x + ev[nt].x + xv.x;
                    const float t1 = (acc[mt][nt][h*2+1] - mu) * rstd * gv[nt].y + ev[nt].y + xv.y;
                    *(float2*)(out + (size_t)rg * C_IN + cbase + nt * 8) =
                        make_float2(t0 * normcdff(t0), t1 * normcdff(t1));
                }
            }
        }
}

extern "C" void kernel_launch(void* const* d_in, const int* in_sizes, int n_in,
                              void* d_out, int out_size)
{
    const float* x     = (const float*)d_in[0];
    const int*   idx1  = (const int*)d_in[1];
    const int*   idx2  = (const int*)d_in[2];
    const int*   idx3  = (const int*)d_in[3];
    const int*   idx4  = (const int*)d_in[4];
    const float* W     = (const float*)d_in[5];
    const float* bias  = (const float*)d_in[6];
    const float* gamma = (const float*)d_in[7];
    const float* beta  = (const float*)d_in[8];
    float* out = (float*)d_out;

    const int n = in_sizes[1];
    const int grid = (n + MT - 1) / MT;

    cudaFuncSetAttribute(smc_mma_kernel,
                         cudaFuncAttributeMaxDynamicSharedMemorySize, SMEM_BYTES);

    prep_w_kernel<<<C_OUT, 256>>>(W);
    smc_mma_kernel<<<grid, NTHREADS, SMEM_BYTES>>>(
        x, idx1, idx2, idx3, idx4, bias, gamma, beta, out, n);
}

// round 6
// speedup vs baseline: 7.4682x; 1.6933x over previous
#include <cuda_runtime.h>
#include <cuda_fp16.h>
#include <cstdint>

#define C_OUT   256
#define C_IN    256
#define K_TOT   1280
#define KCH     64               // k per chunk (fp16) -> 128B per row
#define NCH     (K_TOT / KCH)    // 20
#define MT      128              // rows per CTA
#define NTHREADS 512             // 16 warps: 4x4 warp grid, warp tile 32x64

// dynamic smem: A[2][128*128B] @0 (2x16KB), B[2][256*128B] @32768 (2x32KB)
#define SO_A    0
#define SO_B    32768
#define SMEM_BYTES 98304

// W transposed fp16 scratch: Wt[n][k]
__device__ __half g_Wh[C_OUT * K_TOT];

// ---------------- helpers ----------------
__device__ __forceinline__ uint32_t smem_u32(const void* p) {
    uint32_t a;
    asm("{ .reg .u64 t; cvta.to.shared.u64 t, %1; cvt.u32.u64 %0, t; }" : "=r"(a) : "l"(p));
    return a;
}
__device__ __forceinline__ uint32_t swz(uint32_t b) { return b ^ ((b >> 3) & 0x70); }

__device__ __forceinline__ void ldsm4(uint32_t* r, uint32_t a) {
    asm volatile("ldmatrix.sync.aligned.m8n8.x4.shared.b16 {%0,%1,%2,%3}, [%4];"
                 : "=r"(r[0]), "=r"(r[1]), "=r"(r[2]), "=r"(r[3]) : "r"(a));
}
__device__ __forceinline__ void mma16816(float* c, const uint32_t* a, const uint32_t* b) {
    asm volatile("mma.sync.aligned.m16n8k16.row.col.f32.f16.f16.f32 "
                 "{%0,%1,%2,%3}, {%4,%5,%6,%7}, {%8,%9}, {%0,%1,%2,%3};"
                 : "+f"(c[0]), "+f"(c[1]), "+f"(c[2]), "+f"(c[3])
                 : "r"(a[0]), "r"(a[1]), "r"(a[2]), "r"(a[3]), "r"(b[0]), "r"(b[1]));
}
__device__ __forceinline__ uint32_t pkh2(float a, float b) {
    __half2 h = __floats2half2_rn(a, b);
    return *reinterpret_cast<uint32_t*>(&h);
}
__device__ __forceinline__ void cp_async16(uint32_t saddr, const void* gptr) {
    asm volatile("cp.async.cg.shared.global [%0], [%1], 16;"
                 :: "r"(saddr), "l"(__cvta_generic_to_global(gptr)));
}

// ---------------- prep: W[k][n] fp32 -> Wt fp16 [n][k] ----------------
__global__ void prep_w_kernel(const float* __restrict__ W) {
    const int n = blockIdx.x;
    for (int k = threadIdx.x; k < K_TOT; k += blockDim.x)
        g_Wh[n * K_TOT + k] = __float2half_rn(W[(size_t)k * C_OUT + n]);
}

// ---------------- staging: build A patch chunk + cp.async W chunk ----------------
__device__ __forceinline__ void stage_chunk(char* ds, uint32_t sb, int kc, int tid,
                                            int bRow0, int nRows,
                                            const float* __restrict__ x,
                                            const int (*sIdx)[MT])
{
    const int b = kc & 1;
    const int kg0 = kc * KCH;
    const int seg = kg0 >> 8;            // 0..4 (chunk never crosses segments)
    const int colbase = kg0 & 255;
    char* A = ds + SO_A + b * 16384;
    const uint32_t Bs = sb + SO_B + b * 32768;

    // B: 256 rows x 64 fp16 -> 2048 x 16B cp.async, 4 iters of 512 threads
    #pragma unroll
    for (int it = 0; it < 4; ++it) {
        const int s = tid + it * NTHREADS;
        const int n = s >> 3;
        const int k8 = (s & 7) * 8;
        cp_async16(Bs + swz(n * 128 + k8 * 2), g_Wh + n * K_TOT + kg0 + k8);
    }

    // A: 128 rows x 64 fp16; 1024 x 16B stores -> 2 iters of 512 threads
    #pragma unroll
    for (int it = 0; it < 2; ++it) {
        const int s = tid + it * NTHREADS;
        const int row = s >> 3;
        const int k8 = (s & 7) * 8;
        const int ccol = colbase + k8;
        float v[8];
        if (seg == 0) {
            int rg = bRow0 + row; if (rg >= nRows) rg = nRows - 1;
            const float4 v0 = *(const float4*)(x + (size_t)rg * C_IN + ccol);
            const float4 v1 = *(const float4*)(x + (size_t)rg * C_IN + ccol + 4);
            v[0]=v0.x; v[1]=v0.y; v[2]=v0.z; v[3]=v0.w;
            v[4]=v1.x; v[5]=v1.y; v[6]=v1.z; v[7]=v1.w;
        } else {
            int sA, sB;
            if (seg <= 2) { sA = sIdx[0][row]; sB = sIdx[2][row]; }   // a,c
            else          { sA = sIdx[1][row]; sB = sIdx[3][row]; }   // b,d
            const float4 a0 = *(const float4*)(x + (size_t)sA * C_IN + ccol);
            const float4 a1 = *(const float4*)(x + (size_t)sA * C_IN + ccol + 4);
            const float4 b0 = *(const float4*)(x + (size_t)sB * C_IN + ccol);
            const float4 b1 = *(const float4*)(x + (size_t)sB * C_IN + ccol + 4);
            if (seg & 1) {   // |a-c| or |b-d|
                v[0]=fabsf(a0.x-b0.x); v[1]=fabsf(a0.y-b0.y);
                v[2]=fabsf(a0.z-b0.z); v[3]=fabsf(a0.w-b0.w);
                v[4]=fabsf(a1.x-b1.x); v[5]=fabsf(a1.y-b1.y);
                v[6]=fabsf(a1.z-b1.z); v[7]=fabsf(a1.w-b1.w);
            } else {         // a+c or b+d
                v[0]=a0.x+b0.x; v[1]=a0.y+b0.y; v[2]=a0.z+b0.z; v[3]=a0.w+b0.w;
                v[4]=a1.x+b1.x; v[5]=a1.y+b1.y; v[6]=a1.z+b1.z; v[7]=a1.w+b1.w;
            }
        }
        uint4 w;
        w.x = pkh2(v[0], v[1]); w.y = pkh2(v[2], v[3]);
        w.z = pkh2(v[4], v[5]); w.w = pkh2(v[6], v[7]);
        *(uint4*)(A + swz(row * 128 + k8 * 2)) = w;
    }
}

// ---------------- main kernel ----------------
__global__ void __launch_bounds__(NTHREADS, 1)
smc_mma_kernel(const float* __restrict__ x,
               const int* __restrict__ idx1, const int* __restrict__ idx2,
               const int* __restrict__ idx3, const int* __restrict__ idx4,
               const float* __restrict__ bias, const float* __restrict__ gamma,
               const float* __restrict__ beta,
               float* __restrict__ out, int nRows)
{
    extern __shared__ char ds[];
    __shared__ int    sIdx[4][MT];
    __shared__ float2 sPart[MT][4];

    const uint32_t sb = smem_u32(ds);
    const int tid  = threadIdx.x;
    const int lane = tid & 31;
    const int wid  = tid >> 5;
    const int wm   = wid & 3;     // warp row group (32 rows)
    const int wn   = wid >> 2;    // warp col group (64 cols)
    const int bRow0 = blockIdx.x * MT;

    // neighbor indices
    {
        const int a = tid >> 7, r = tid & 127;
        int rg = bRow0 + r; if (rg >= nRows) rg = nRows - 1;
        const int* ip = (a == 0) ? idx1 : (a == 1) ? idx2 : (a == 2) ? idx3 : idx4;
        sIdx[a][r] = ip[rg];
    }
    __syncthreads();

    float acc[2][8][4];
    #pragma unroll
    for (int i = 0; i < 2; i++)
        #pragma unroll
        for (int j = 0; j < 8; j++)
            #pragma unroll
            for (int e = 0; e < 4; e++) acc[i][j][e] = 0.f;

    // per-lane ldmatrix address components
    const int lA_row = wm * 32 + (lane & 7) + ((lane >> 3) & 1) * 8; // + mt*16
    const int lA_k8  = ((lane >> 4) & 1) * 8;
    const int lB_n   = wn * 64 + (lane & 7) + ((lane >> 4) & 1) * 8; // + ng*16
    const int lB_k8  = ((lane >> 3) & 1) * 8;

    stage_chunk(ds, sb, 0, tid, bRow0, nRows, x, sIdx);
    asm volatile("cp.async.wait_all;" ::: "memory");
    __syncthreads();

    for (int kc = 0; kc < NCH; ++kc) {
        if (kc + 1 < NCH)
            stage_chunk(ds, sb, kc + 1, tid, bRow0, nRows, x, sIdx);

        const uint32_t Ab = sb + SO_A + (kc & 1) * 16384;
        const uint32_t Bb = sb + SO_B + (kc & 1) * 32768;

        #pragma unroll
        for (int ks = 0; ks < 4; ++ks) {
            const int kb = ks * 16;
            uint32_t a0[4], a1[4];
            ldsm4(a0, Ab + swz((uint32_t)(lA_row        * 128 + (kb + lA_k8) * 2)));
            ldsm4(a1, Ab + swz((uint32_t)((lA_row + 16) * 128 + (kb + lA_k8) * 2)));
            #pragma unroll
            for (int ng = 0; ng < 4; ++ng) {
                const uint32_t boff = swz((uint32_t)((lB_n + ng * 16) * 128 + (kb + lB_k8) * 2));
                uint32_t bh[4];
                ldsm4(bh, Bb + boff);
                mma16816(acc[0][2*ng+0], a0, bh + 0);
                mma16816(acc[0][2*ng+1], a0, bh + 2);
                mma16816(acc[1][2*ng+0], a1, bh + 0);
                mma16816(acc[1][2*ng+1], a1, bh + 2);
            }
        }
        asm volatile("cp.async.wait_all;" ::: "memory");
        __syncthreads();
    }

    // ---------------- epilogue: bias + LN + residual + exact GELU ----------------
    const int cbase = wn * 64 + (lane & 3) * 2;

    #pragma unroll
    for (int nt = 0; nt < 8; ++nt) {
        const float2 bv = *(const float2*)(bias + cbase + nt * 8);
        #pragma unroll
        for (int mt = 0; mt < 2; ++mt) {
            acc[mt][nt][0] += bv.x; acc[mt][nt][1] += bv.y;
            acc[mt][nt][2] += bv.x; acc[mt][nt][3] += bv.y;
        }
    }

    #pragma unroll
    for (int mt = 0; mt < 2; ++mt)
        #pragma unroll
        for (int h = 0; h < 2; ++h) {
            float s = 0.f, s2 = 0.f;
            #pragma unroll
            for (int nt = 0; nt < 8; ++nt) {
                const float y0 = acc[mt][nt][h*2], y1 = acc[mt][nt][h*2+1];
                s += y0 + y1; s2 += y0*y0 + y1*y1;
            }
            s  += __shfl_xor_sync(0xffffffffu, s, 1);
            s2 += __shfl_xor_sync(0xffffffffu, s2, 1);
            s  += __shfl_xor_sync(0xffffffffu, s, 2);
            s2 += __shfl_xor_sync(0xffffffffu, s2, 2);
            if ((lane & 3) == 0) {
                const int row = wm * 32 + mt * 16 + h * 8 + (lane >> 2);
                sPart[row][wn] = make_float2(s, s2);
            }
        }
    __syncthreads();

    float2 gv[8], ev[8];
    #pragma unroll
    for (int nt = 0; nt < 8; ++nt) {
        gv[nt] = *(const float2*)(gamma + cbase + nt * 8);
        ev[nt] = *(const float2*)(beta  + cbase + nt * 8);
    }

    #pragma unroll
    for (int mt = 0; mt < 2; ++mt)
        #pragma unroll
        for (int h = 0; h < 2; ++h) {
            const int row = wm * 32 + mt * 16 + h * 8 + (lane >> 2);
            const float2 p0 = sPart[row][0], p1 = sPart[row][1];
            const float2 p2 = sPart[row][2], p3 = sPart[row][3];
            const float S  = p0.x + p1.x + p2.x + p3.x;
            const float S2 = p0.y + p1.y + p2.y + p3.y;
            const float mu = S * (1.0f / 256.0f);
            const float var = S2 * (1.0f / 256.0f) - mu * mu;
            const float rstd = rsqrtf(var + 1e-5f);
            const int rg = bRow0 + row;
            if (rg < nRows) {
                #pragma unroll
                for (int nt = 0; nt < 8; ++nt) {
                    const float2 xv = *(const float2*)(x + (size_t)rg * C_IN + cbase + nt * 8);
                    const float t0 = (acc[mt][nt][h*2]   - mu) * rstd * gv[nt].x + ev[nt].x + xv.x;
                    const float t1 = (acc[mt][nt][h*2+1] - mu) * rstd * gv[nt].y + ev[nt].y + xv.y;
                    *(float2*)(out + (size_t)rg * C_IN + cbase + nt * 8) =
                        make_float2(t0 * normcdff(t0), t1 * normcdff(t1));
                }
            }
        }
}

extern "C" void kernel_launch(void* const* d_in, const int* in_sizes, int n_in,
                              void* d_out, int out_size)
{
    const float* x     = (const float*)d_in[0];
    const int*   idx1  = (const int*)d_in[1];
    const int*   idx2  = (const int*)d_in[2];
    const int*   idx3  = (const int*)d_in[3];
    const int*   idx4  = (const int*)d_in[4];
    const float* W     = (const float*)d_in[5];
    const float* bias  = (const float*)d_in[6];
    const float* gamma = (const float*)d_in[7];
    const float* beta  = (const float*)d_in[8];
    float* out = (float*)d_out;

    const int n = in_sizes[1];
    const int grid = (n + MT - 1) / MT;

    cudaFuncSetAttribute(smc_mma_kernel,
                         cudaFuncAttributeMaxDynamicSharedMemorySize, SMEM_BYTES);

    prep_w_kernel<<<C_OUT, 256>>>(W);
    smc_mma_kernel<<<grid, NTHREADS, SMEM_BYTES>>>(
        x, idx1, idx2, idx3, idx4, bias, gamma, beta, out, n);
}

// round 7
// speedup vs baseline: 7.4695x; 1.0002x over previous
#include <cuda_runtime.h>
#include <cuda_fp16.h>
#include <cstdint>

#define C_OUT   256
#define C_IN    256
#define K_TOT   1280
#define KCH     64               // k per chunk (fp16) -> 128B per row
#define NCH     (K_TOT / KCH)    // 20
#define MT      128              // rows per CTA
#define NTHREADS 512             // 16 warps: 4x4 warp grid, warp tile 32x64

// dynamic smem: A[2][128*128B] @0 (2x16KB), B[2][256*128B] @32768 (2x32KB)
#define SO_A    0
#define SO_B    32768
#define SMEM_BYTES 98304

// W transposed fp16 scratch: Wt[n][k]
__device__ __half g_Wh[C_OUT * K_TOT];

// ---------------- helpers ----------------
__device__ __forceinline__ uint32_t smem_u32(const void* p) {
    uint32_t a;
    asm("{ .reg .u64 t; cvta.to.shared.u64 t, %1; cvt.u32.u64 %0, t; }" : "=r"(a) : "l"(p));
    return a;
}
__device__ __forceinline__ uint32_t swz(uint32_t b) { return b ^ ((b >> 3) & 0x70); }

__device__ __forceinline__ void ldsm4(uint32_t* r, uint32_t a) {
    asm volatile("ldmatrix.sync.aligned.m8n8.x4.shared.b16 {%0,%1,%2,%3}, [%4];"
                 : "=r"(r[0]), "=r"(r[1]), "=r"(r[2]), "=r"(r[3]) : "r"(a));
}
__device__ __forceinline__ void mma16816(float* c, const uint32_t* a, const uint32_t* b) {
    asm volatile("mma.sync.aligned.m16n8k16.row.col.f32.f16.f16.f32 "
                 "{%0,%1,%2,%3}, {%4,%5,%6,%7}, {%8,%9}, {%0,%1,%2,%3};"
                 : "+f"(c[0]), "+f"(c[1]), "+f"(c[2]), "+f"(c[3])
                 : "r"(a[0]), "r"(a[1]), "r"(a[2]), "r"(a[3]), "r"(b[0]), "r"(b[1]));
}
__device__ __forceinline__ uint32_t pkh2(float a, float b) {
    __half2 h = __floats2half2_rn(a, b);
    return *reinterpret_cast<uint32_t*>(&h);
}
__device__ __forceinline__ void cp_async16(uint32_t saddr, const void* gptr) {
    asm volatile("cp.async.cg.shared.global [%0], [%1], 16;"
                 :: "r"(saddr), "l"(__cvta_generic_to_global(gptr)));
}

// ---------------- prep: W[k][n] fp32 -> Wt fp16 [n][k] ----------------
__global__ void prep_w_kernel(const float* __restrict__ W) {
    const int n = blockIdx.x;
    for (int k = threadIdx.x; k < K_TOT; k += blockDim.x)
        g_Wh[n * K_TOT + k] = __float2half_rn(W[(size_t)k * C_OUT + n]);
}

// ---------------- staging: build A patch chunk + cp.async W chunk ----------------
__device__ __forceinline__ void stage_chunk(char* ds, uint32_t sb, int kc, int tid,
                                            int bRow0, int nRows,
                                            const float* __restrict__ x,
                                            const int (*sIdx)[MT])
{
    const int b = kc & 1;
    const int kg0 = kc * KCH;
    const int seg = kg0 >> 8;            // 0..4 (chunk never crosses segments)
    const int colbase = kg0 & 255;
    char* A = ds + SO_A + b * 16384;
    const uint32_t Bs = sb + SO_B + b * 32768;

    // B: 256 rows x 64 fp16 -> 2048 x 16B cp.async, 4 iters of 512 threads
    #pragma unroll
    for (int it = 0; it < 4; ++it) {
        const int s = tid + it * NTHREADS;
        const int n = s >> 3;
        const int k8 = (s & 7) * 8;
        cp_async16(Bs + swz(n * 128 + k8 * 2), g_Wh + n * K_TOT + kg0 + k8);
    }

    // A: 128 rows x 64 fp16; 1024 x 16B stores -> 2 iters of 512 threads
    #pragma unroll
    for (int it = 0; it < 2; ++it) {
        const int s = tid + it * NTHREADS;
        const int row = s >> 3;
        const int k8 = (s & 7) * 8;
        const int ccol = colbase + k8;
        float v[8];
        if (seg == 0) {
            int rg = bRow0 + row; if (rg >= nRows) rg = nRows - 1;
            const float4 v0 = *(const float4*)(x + (size_t)rg * C_IN + ccol);
            const float4 v1 = *(const float4*)(x + (size_t)rg * C_IN + ccol + 4);
            v[0]=v0.x; v[1]=v0.y; v[2]=v0.z; v[3]=v0.w;
            v[4]=v1.x; v[5]=v1.y; v[6]=v1.z; v[7]=v1.w;
        } else {
            int sA, sB;
            if (seg <= 2) { sA = sIdx[0][row]; sB = sIdx[2][row]; }   // a,c
            else          { sA = sIdx[1][row]; sB = sIdx[3][row]; }   // b,d
            const float4 a0 = *(const float4*)(x + (size_t)sA * C_IN + ccol);
            const float4 a1 = *(const float4*)(x + (size_t)sA * C_IN + ccol + 4);
            const float4 b0 = *(const float4*)(x + (size_t)sB * C_IN + ccol);
            const float4 b1 = *(const float4*)(x + (size_t)sB * C_IN + ccol + 4);
            if (seg & 1) {   // |a-c| or |b-d|
                v[0]=fabsf(a0.x-b0.x); v[1]=fabsf(a0.y-b0.y);
                v[2]=fabsf(a0.z-b0.z); v[3]=fabsf(a0.w-b0.w);
                v[4]=fabsf(a1.x-b1.x); v[5]=fabsf(a1.y-b1.y);
                v[6]=fabsf(a1.z-b1.z); v[7]=fabsf(a1.w-b1.w);
            } else {         // a+c or b+d
                v[0]=a0.x+b0.x; v[1]=a0.y+b0.y; v[2]=a0.z+b0.z; v[3]=a0.w+b0.w;
                v[4]=a1.x+b1.x; v[5]=a1.y+b1.y; v[6]=a1.z+b1.z; v[7]=a1.w+b1.w;
            }
        }
        uint4 w;
        w.x = pkh2(v[0], v[1]); w.y = pkh2(v[2], v[3]);
        w.z = pkh2(v[4], v[5]); w.w = pkh2(v[6], v[7]);
        *(uint4*)(A + swz(row * 128 + k8 * 2)) = w;
    }
}

// ---------------- main kernel ----------------
__global__ void __launch_bounds__(NTHREADS, 1)
smc_mma_kernel(const float* __restrict__ x,
               const int* __restrict__ idx1, const int* __restrict__ idx2,
               const int* __restrict__ idx3, const int* __restrict__ idx4,
               const float* __restrict__ bias, const float* __restrict__ gamma,
               const float* __restrict__ beta,
               float* __restrict__ out, int nRows)
{
    extern __shared__ char ds[];
    __shared__ int    sIdx[4][MT];
    __shared__ float2 sPart[MT][4];

    const uint32_t sb = smem_u32(ds);
    const int tid  = threadIdx.x;
    const int lane = tid & 31;
    const int wid  = tid >> 5;
    const int wm   = wid & 3;     // warp row group (32 rows)
    const int wn   = wid >> 2;    // warp col group (64 cols)
    const int bRow0 = blockIdx.x * MT;

    // neighbor indices
    {
        const int a = tid >> 7, r = tid & 127;
        int rg = bRow0 + r; if (rg >= nRows) rg = nRows - 1;
        const int* ip = (a == 0) ? idx1 : (a == 1) ? idx2 : (a == 2) ? idx3 : idx4;
        sIdx[a][r] = ip[rg];
    }
    __syncthreads();

    float acc[2][8][4];
    #pragma unroll
    for (int i = 0; i < 2; i++)
        #pragma unroll
        for (int j = 0; j < 8; j++)
            #pragma unroll
            for (int e = 0; e < 4; e++) acc[i][j][e] = 0.f;

    // per-lane ldmatrix address components
    const int lA_row = wm * 32 + (lane & 7) + ((lane >> 3) & 1) * 8; // + mt*16
    const int lA_k8  = ((lane >> 4) & 1) * 8;
    const int lB_n   = wn * 64 + (lane & 7) + ((lane >> 4) & 1) * 8; // + ng*16
    const int lB_k8  = ((lane >> 3) & 1) * 8;

    stage_chunk(ds, sb, 0, tid, bRow0, nRows, x, sIdx);
    asm volatile("cp.async.wait_all;" ::: "memory");
    __syncthreads();

    for (int kc = 0; kc < NCH; ++kc) {
        if (kc + 1 < NCH)
            stage_chunk(ds, sb, kc + 1, tid, bRow0, nRows, x, sIdx);

        const uint32_t Ab = sb + SO_A + (kc & 1) * 16384;
        const uint32_t Bb = sb + SO_B + (kc & 1) * 32768;

        #pragma unroll
        for (int ks = 0; ks < 4; ++ks) {
            const int kb = ks * 16;
            uint32_t a0[4], a1[4];
            ldsm4(a0, Ab + swz((uint32_t)(lA_row        * 128 + (kb + lA_k8) * 2)));
            ldsm4(a1, Ab + swz((uint32_t)((lA_row + 16) * 128 + (kb + lA_k8) * 2)));
            #pragma unroll
            for (int ng = 0; ng < 4; ++ng) {
                const uint32_t boff = swz((uint32_t)((lB_n + ng * 16) * 128 + (kb + lB_k8) * 2));
                uint32_t bh[4];
                ldsm4(bh, Bb + boff);
                mma16816(acc[0][2*ng+0], a0, bh + 0);
                mma16816(acc[0][2*ng+1], a0, bh + 2);
                mma16816(acc[1][2*ng+0], a1, bh + 0);
                mma16816(acc[1][2*ng+1], a1, bh + 2);
            }
        }
        asm volatile("cp.async.wait_all;" ::: "memory");
        __syncthreads();
    }

    // ---------------- epilogue: bias + LN + residual + exact GELU ----------------
    const int cbase = wn * 64 + (lane & 3) * 2;

    #pragma unroll
    for (int nt = 0; nt < 8; ++nt) {
        const float2 bv = *(const float2*)(bias + cbase + nt * 8);
        #pragma unroll
        for (int mt = 0; mt < 2; ++mt) {
            acc[mt][nt][0] += bv.x; acc[mt][nt][1] += bv.y;
            acc[mt][nt][2] += bv.x; acc[mt][nt][3] += bv.y;
        }
    }

    #pragma unroll
    for (int mt = 0; mt < 2; ++mt)
        #pragma unroll
        for (int h = 0; h < 2; ++h) {
            float s = 0.f, s2 = 0.f;
            #pragma unroll
            for (int nt = 0; nt < 8; ++nt) {
                const float y0 = acc[mt][nt][h*2], y1 = acc[mt][nt][h*2+1];
                s += y0 + y1; s2 += y0*y0 + y1*y1;
            }
            s  += __shfl_xor_sync(0xffffffffu, s, 1);
            s2 += __shfl_xor_sync(0xffffffffu, s2, 1);
            s  += __shfl_xor_sync(0xffffffffu, s, 2);
            s2 += __shfl_xor_sync(0xffffffffu, s2, 2);
            if ((lane & 3) == 0) {
                const int row = wm * 32 + mt * 16 + h * 8 + (lane >> 2);
                sPart[row][wn] = make_float2(s, s2);
            }
        }
    __syncthreads();

    float2 gv[8], ev[8];
    #pragma unroll
    for (int nt = 0; nt < 8; ++nt) {
        gv[nt] = *(const float2*)(gamma + cbase + nt * 8);
        ev[nt] = *(const float2*)(beta  + cbase + nt * 8);
    }

    #pragma unroll
    for (int mt = 0; mt < 2; ++mt)
        #pragma unroll
        for (int h = 0; h < 2; ++h) {
            const int row = wm * 32 + mt * 16 + h * 8 + (lane >> 2);
            const float2 p0 = sPart[row][0], p1 = sPart[row][1];
            const float2 p2 = sPart[row][2], p3 = sPart[row][3];
            const float S  = p0.x + p1.x + p2.x + p3.x;
            const float S2 = p0.y + p1.y + p2.y + p3.y;
            const float mu = S * (1.0f / 256.0f);
            const float var = S2 * (1.0f / 256.0f) - mu * mu;
            const float rstd = rsqrtf(var + 1e-5f);
            const int rg = bRow0 + row;
            if (rg < nRows) {
                #pragma unroll
                for (int nt = 0; nt < 8; ++nt) {
                    const float2 xv = *(const float2*)(x + (size_t)rg * C_IN + cbase + nt * 8);
                    const float t0 = (acc[mt][nt][h*2]   - mu) * rstd * gv[nt].x + ev[nt].x + xv.x;
                    const float t1 = (acc[mt][nt][h*2+1] - mu) * rstd * gv[nt].y + ev[nt].y + xv.y;
                    *(float2*)(out + (size_t)rg * C_IN + cbase + nt * 8) =
                        make_float2(t0 * normcdff(t0), t1 * normcdff(t1));
                }
            }
        }
}

extern "C" void kernel_launch(void* const* d_in, const int* in_sizes, int n_in,
                              void* d_out, int out_size)
{
    const float* x     = (const float*)d_in[0];
    const int*   idx1  = (const int*)d_in[1];
    const int*   idx2  = (const int*)d_in[2];
    const int*   idx3  = (const int*)d_in[3];
    const int*   idx4  = (const int*)d_in[4];
    const float* W     = (const float*)d_in[5];
    const float* bias  = (const float*)d_in[6];
    const float* gamma = (const float*)d_in[7];
    const float* beta  = (const float*)d_in[8];
    float* out = (float*)d_out;

    const int n = in_sizes[1];
    const int grid = (n + MT - 1) / MT;

    cudaFuncSetAttribute(smc_mma_kernel,
                         cudaFuncAttributeMaxDynamicSharedMemorySize, SMEM_BYTES);

    prep_w_kernel<<<C_OUT, 256>>>(W);
    smc_mma_kernel<<<grid, NTHREADS, SMEM_BYTES>>>(
        x, idx1, idx2, idx3, idx4, bias, gamma, beta, out, n);
}

// round 8
// speedup vs baseline: 8.5150x; 1.1400x over previous
#include <cuda_runtime.h>
#include <cuda_fp16.h>
#include <cstdint>

#define C_OUT   256
#define C_IN    256
#define K_TOT   1280
#define KCH     64               // k per chunk (fp16) -> 128B per row
#define NCH     (K_TOT / KCH)    // 20
#define MT      64               // rows per CTA
#define NTHREADS 256             // 8 warps: 2x4 warp grid, warp tile 32x64

// dynamic smem: A[2][64*128B] @0 (2x8KB), B[2][256*128B] @16384 (2x32KB)
#define SO_A    0
#define SO_B    16384
#define SMEM_BYTES 81920

// W transposed fp16 scratch: Wt[n][k]
__device__ __half g_Wh[C_OUT * K_TOT];

// ---------------- helpers ----------------
__device__ __forceinline__ uint32_t smem_u32(const void* p) {
    uint32_t a;
    asm("{ .reg .u64 t; cvta.to.shared.u64 t, %1; cvt.u32.u64 %0, t; }" : "=r"(a) : "l"(p));
    return a;
}
__device__ __forceinline__ uint32_t swz(uint32_t b) { return b ^ ((b >> 3) & 0x70); }

__device__ __forceinline__ void ldsm4(uint32_t* r, uint32_t a) {
    asm volatile("ldmatrix.sync.aligned.m8n8.x4.shared.b16 {%0,%1,%2,%3}, [%4];"
                 : "=r"(r[0]), "=r"(r[1]), "=r"(r[2]), "=r"(r[3]) : "r"(a));
}
__device__ __forceinline__ void mma16816(float* c, const uint32_t* a, const uint32_t* b) {
    asm volatile("mma.sync.aligned.m16n8k16.row.col.f32.f16.f16.f32 "
                 "{%0,%1,%2,%3}, {%4,%5,%6,%7}, {%8,%9}, {%0,%1,%2,%3};"
                 : "+f"(c[0]), "+f"(c[1]), "+f"(c[2]), "+f"(c[3])
                 : "r"(a[0]), "r"(a[1]), "r"(a[2]), "r"(a[3]), "r"(b[0]), "r"(b[1]));
}
__device__ __forceinline__ uint32_t pkh2(float a, float b) {
    __half2 h = __floats2half2_rn(a, b);
    return *reinterpret_cast<uint32_t*>(&h);
}
__device__ __forceinline__ void cp_async16(uint32_t saddr, const void* gptr) {
    asm volatile("cp.async.cg.shared.global [%0], [%1], 16;"
                 :: "r"(saddr), "l"(__cvta_generic_to_global(gptr)));
}

// ---------------- prep: W[k][n] fp32 -> Wt fp16 [n][k] ----------------
__global__ void prep_w_kernel(const float* __restrict__ W) {
    const int n = blockIdx.x;
    for (int k = threadIdx.x; k < K_TOT; k += blockDim.x)
        g_Wh[n * K_TOT + k] = __float2half_rn(W[(size_t)k * C_OUT + n]);
}

// ---------------- staging: build A patch chunk + cp.async W chunk ----------------
__device__ __forceinline__ void stage_chunk(char* ds, uint32_t sb, int kc, int tid,
                                            int bRow0, int nRows,
                                            const float* __restrict__ x,
                                            const int (*sIdx)[MT])
{
    const int b = kc & 1;
    const int kg0 = kc * KCH;
    const int seg = kg0 >> 8;            // 0..4 (chunk never crosses segments)
    const int colbase = kg0 & 255;
    char* A = ds + SO_A + b * 8192;
    const uint32_t Bs = sb + SO_B + b * 32768;

    // B: 256 rows x 64 fp16 -> 2048 x 16B cp.async, 8 iters of 256 threads
    #pragma unroll
    for (int it = 0; it < 8; ++it) {
        const int s = tid + it * NTHREADS;
        const int n = s >> 3;
        const int k8 = (s & 7) * 8;
        cp_async16(Bs + swz(n * 128 + k8 * 2), g_Wh + n * K_TOT + kg0 + k8);
    }

    // A: 64 rows x 64 fp16; 512 x 16B stores -> 2 iters of 256 threads
    #pragma unroll
    for (int it = 0; it < 2; ++it) {
        const int s = tid + it * NTHREADS;
        const int row = s >> 3;
        const int k8 = (s & 7) * 8;
        const int ccol = colbase + k8;
        float v[8];
        if (seg == 0) {
            int rg = bRow0 + row; if (rg >= nRows) rg = nRows - 1;
            const float4 v0 = *(const float4*)(x + (size_t)rg * C_IN + ccol);
            const float4 v1 = *(const float4*)(x + (size_t)rg * C_IN + ccol + 4);
            v[0]=v0.x; v[1]=v0.y; v[2]=v0.z; v[3]=v0.w;
            v[4]=v1.x; v[5]=v1.y; v[6]=v1.z; v[7]=v1.w;
        } else {
            int sA, sB;
            if (seg <= 2) { sA = sIdx[0][row]; sB = sIdx[2][row]; }   // a,c
            else          { sA = sIdx[1][row]; sB = sIdx[3][row]; }   // b,d
            const float4 a0 = *(const float4*)(x + (size_t)sA * C_IN + ccol);
            const float4 a1 = *(const float4*)(x + (size_t)sA * C_IN + ccol + 4);
            const float4 b0 = *(const float4*)(x + (size_t)sB * C_IN + ccol);
            const float4 b1 = *(const float4*)(x + (size_t)sB * C_IN + ccol + 4);
            if (seg & 1) {   // |a-c| or |b-d|
                v[0]=fabsf(a0.x-b0.x); v[1]=fabsf(a0.y-b0.y);
                v[2]=fabsf(a0.z-b0.z); v[3]=fabsf(a0.w-b0.w);
                v[4]=fabsf(a1.x-b1.x); v[5]=fabsf(a1.y-b1.y);
                v[6]=fabsf(a1.z-b1.z); v[7]=fabsf(a1.w-b1.w);
            } else {         // a+c or b+d
                v[0]=a0.x+b0.x; v[1]=a0.y+b0.y; v[2]=a0.z+b0.z; v[3]=a0.w+b0.w;
                v[4]=a1.x+b1.x; v[5]=a1.y+b1.y; v[6]=a1.z+b1.z; v[7]=a1.w+b1.w;
            }
        }
        uint4 w;
        w.x = pkh2(v[0], v[1]); w.y = pkh2(v[2], v[3]);
        w.z = pkh2(v[4], v[5]); w.w = pkh2(v[6], v[7]);
        *(uint4*)(A + swz(row * 128 + k8 * 2)) = w;
    }
}

// ---------------- main kernel ----------------
__global__ void __launch_bounds__(NTHREADS, 2)
smc_mma_kernel(const float* __restrict__ x,
               const int* __restrict__ idx1, const int* __restrict__ idx2,
               const int* __restrict__ idx3, const int* __restrict__ idx4,
               const float* __restrict__ bias, const float* __restrict__ gamma,
               const float* __restrict__ beta,
               float* __restrict__ out, int nRows)
{
    extern __shared__ char ds[];
    __shared__ int    sIdx[4][MT];
    __shared__ float2 sPart[MT][4];

    const uint32_t sb = smem_u32(ds);
    const int tid  = threadIdx.x;
    const int lane = tid & 31;
    const int wid  = tid >> 5;
    const int wm   = wid & 1;     // warp row group (32 rows)
    const int wn   = wid >> 1;    // warp col group (64 cols)
    const int bRow0 = blockIdx.x * MT;

    // neighbor indices: 4 arrays x 64 rows = 256 loads
    {
        const int a = tid >> 6, r = tid & 63;
        int rg = bRow0 + r; if (rg >= nRows) rg = nRows - 1;
        const int* ip = (a == 0) ? idx1 : (a == 1) ? idx2 : (a == 2) ? idx3 : idx4;
        sIdx[a][r] = ip[rg];
    }
    __syncthreads();

    float acc[2][8][4];
    #pragma unroll
    for (int i = 0; i < 2; i++)
        #pragma unroll
        for (int j = 0; j < 8; j++)
            #pragma unroll
            for (int e = 0; e < 4; e++) acc[i][j][e] = 0.f;

    // per-lane ldmatrix address components
    const int lA_row = wm * 32 + (lane & 7) + ((lane >> 3) & 1) * 8; // + mt*16
    const int lA_k8  = ((lane >> 4) & 1) * 8;
    const int lB_n   = wn * 64 + (lane & 7) + ((lane >> 4) & 1) * 8; // + ng*16
    const int lB_k8  = ((lane >> 3) & 1) * 8;

    stage_chunk(ds, sb, 0, tid, bRow0, nRows, x, sIdx);
    asm volatile("cp.async.wait_all;" ::: "memory");
    __syncthreads();

    for (int kc = 0; kc < NCH; ++kc) {
        if (kc + 1 < NCH)
            stage_chunk(ds, sb, kc + 1, tid, bRow0, nRows, x, sIdx);

        const uint32_t Ab = sb + SO_A + (kc & 1) * 8192;
        const uint32_t Bb = sb + SO_B + (kc & 1) * 32768;

        #pragma unroll
        for (int ks = 0; ks < 4; ++ks) {
            const int kb = ks * 16;
            uint32_t a0[4], a1[4];
            ldsm4(a0, Ab + swz((uint32_t)(lA_row        * 128 + (kb + lA_k8) * 2)));
            ldsm4(a1, Ab + swz((uint32_t)((lA_row + 16) * 128 + (kb + lA_k8) * 2)));
            #pragma unroll
            for (int ng = 0; ng < 4; ++ng) {
                const uint32_t boff = swz((uint32_t)((lB_n + ng * 16) * 128 + (kb + lB_k8) * 2));
                uint32_t bh[4];
                ldsm4(bh, Bb + boff);
                mma16816(acc[0][2*ng+0], a0, bh + 0);
                mma16816(acc[0][2*ng+1], a0, bh + 2);
                mma16816(acc[1][2*ng+0], a1, bh + 0);
                mma16816(acc[1][2*ng+1], a1, bh + 2);
            }
        }
        asm volatile("cp.async.wait_all;" ::: "memory");
        __syncthreads();
    }

    // ---------------- epilogue: bias + LN + residual + exact GELU ----------------
    const int cbase = wn * 64 + (lane & 3) * 2;

    #pragma unroll
    for (int nt = 0; nt < 8; ++nt) {
        const float2 bv = *(const float2*)(bias + cbase + nt * 8);
        #pragma unroll
        for (int mt = 0; mt < 2; ++mt) {
            acc[mt][nt][0] += bv.x; acc[mt][nt][1] += bv.y;
            acc[mt][nt][2] += bv.x; acc[mt][nt][3] += bv.y;
        }
    }

    #pragma unroll
    for (int mt = 0; mt < 2; ++mt)
        #pragma unroll
        for (int h = 0; h < 2; ++h) {
            float s = 0.f, s2 = 0.f;
            #pragma unroll
            for (int nt = 0; nt < 8; ++nt) {
                const float y0 = acc[mt][nt][h*2], y1 = acc[mt][nt][h*2+1];
                s += y0 + y1; s2 += y0*y0 + y1*y1;
            }
            s  += __shfl_xor_sync(0xffffffffu, s, 1);
            s2 += __shfl_xor_sync(0xffffffffu, s2, 1);
            s  += __shfl_xor_sync(0xffffffffu, s, 2);
            s2 += __shfl_xor_sync(0xffffffffu, s2, 2);
            if ((lane & 3) == 0) {
                const int row = wm * 32 + mt * 16 + h * 8 + (lane >> 2);
                sPart[row][wn] = make_float2(s, s2);
            }
        }
    __syncthreads();

    float2 gv[8], ev[8];
    #pragma unroll
    for (int nt = 0; nt < 8; ++nt) {
        gv[nt] = *(const float2*)(gamma + cbase + nt * 8);
        ev[nt] = *(const float2*)(beta  + cbase + nt * 8);
    }

    #pragma unroll
    for (int mt = 0; mt < 2; ++mt)
        #pragma unroll
        for (int h = 0; h < 2; ++h) {
            const int row = wm * 32 + mt * 16 + h * 8 + (lane >> 2);
            const float2 p0 = sPart[row][0], p1 = sPart[row][1];
            const float2 p2 = sPart[row][2], p3 = sPart[row][3];
            const float S  = p0.x + p1.x + p2.x + p3.x;
            const float S2 = p0.y + p1.y + p2.y + p3.y;
            const float mu = S * (1.0f / 256.0f);
            const float var = S2 * (1.0f / 256.0f) - mu * mu;
            const float rstd = rsqrtf(var + 1e-5f);
            const int rg = bRow0 + row;
            if (rg < nRows) {
                #pragma unroll
                for (int nt = 0; nt < 8; ++nt) {
                    const float2 xv = *(const float2*)(x + (size_t)rg * C_IN + cbase + nt * 8);
                    const float t0 = (acc[mt][nt][h*2]   - mu) * rstd * gv[nt].x + ev[nt].x + xv.x;
                    const float t1 = (acc[mt][nt][h*2+1] - mu) * rstd * gv[nt].y + ev[nt].y + xv.y;
                    *(float2*)(out + (size_t)rg * C_IN + cbase + nt * 8) =
                        make_float2(t0 * normcdff(t0), t1 * normcdff(t1));
                }
            }
        }
}

extern "C" void kernel_launch(void* const* d_in, const int* in_sizes, int n_in,
                              void* d_out, int out_size)
{
    const float* x     = (const float*)d_in[0];
    const int*   idx1  = (const int*)d_in[1];
    const int*   idx2  = (const int*)d_in[2];
    const int*   idx3  = (const int*)d_in[3];
    const int*   idx4  = (const int*)d_in[4];
    const float* W     = (const float*)d_in[5];
    const float* bias  = (const float*)d_in[6];
    const float* gamma = (const float*)d_in[7];
    const float* beta  = (const float*)d_in[8];
    float* out = (float*)d_out;

    const int n = in_sizes[1];
    const int grid = (n + MT - 1) / MT;

    cudaFuncSetAttribute(smc_mma_kernel,
                         cudaFuncAttributeMaxDynamicSharedMemorySize, SMEM_BYTES);

    prep_w_kernel<<<C_OUT, 256>>>(W);
    smc_mma_kernel<<<grid, NTHREADS, SMEM_BYTES>>>(
        x, idx1, idx2, idx3, idx4, bias, gamma, beta, out, n);
}

// round 9
// speedup vs baseline: 8.6826x; 1.0197x over previous
#include <cuda_runtime.h>
#include <cuda_fp16.h>
#include <cstdint>

#define C_OUT   256
#define C_IN    256
#define K_TOT   1280
#define KCH     64               // k per chunk (fp16) -> 128B per row
#define NCH     (K_TOT / KCH)    // 20
#define MT      64               // rows per CTA
#define NTHREADS 256             // 8 warps: 2x4 warp grid, warp tile 32x64
#define PN_MAX  100352           // padded max rows for patch scratch

// dynamic smem: A[2][64*128B] @0 (2x8KB), B[2][256*128B] @16384 (2x32KB)
#define SO_A    0
#define SO_B    16384
#define SMEM_BYTES 81920

// W transposed fp16 scratch: Wt[n][k]
__device__ __half g_Wh[C_OUT * K_TOT];
// precomputed fp16 patch [N][1280]
__device__ __half g_patch[(size_t)PN_MAX * K_TOT];

// ---------------- helpers ----------------
__device__ __forceinline__ uint32_t smem_u32(const void* p) {
    uint32_t a;
    asm("{ .reg .u64 t; cvta.to.shared.u64 t, %1; cvt.u32.u64 %0, t; }" : "=r"(a) : "l"(p));
    return a;
}
__device__ __forceinline__ uint32_t swz(uint32_t b) { return b ^ ((b >> 3) & 0x70); }

__device__ __forceinline__ void ldsm4(uint32_t* r, uint32_t a) {
    asm volatile("ldmatrix.sync.aligned.m8n8.x4.shared.b16 {%0,%1,%2,%3}, [%4];"
                 : "=r"(r[0]), "=r"(r[1]), "=r"(r[2]), "=r"(r[3]) : "r"(a));
}
__device__ __forceinline__ void mma16816(float* c, const uint32_t* a, const uint32_t* b) {
    asm volatile("mma.sync.aligned.m16n8k16.row.col.f32.f16.f16.f32 "
                 "{%0,%1,%2,%3}, {%4,%5,%6,%7}, {%8,%9}, {%0,%1,%2,%3};"
                 : "+f"(c[0]), "+f"(c[1]), "+f"(c[2]), "+f"(c[3])
                 : "r"(a[0]), "r"(a[1]), "r"(a[2]), "r"(a[3]), "r"(b[0]), "r"(b[1]));
}
__device__ __forceinline__ uint32_t pkh2(float a, float b) {
    __half2 h = __floats2half2_rn(a, b);
    return *reinterpret_cast<uint32_t*>(&h);
}
__device__ __forceinline__ void cp_async16(uint32_t saddr, const void* gptr) {
    asm volatile("cp.async.cg.shared.global [%0], [%1], 16;"
                 :: "r"(saddr), "l"(__cvta_generic_to_global(gptr)));
}

// ---------------- prep: W[k][n] fp32 -> Wt fp16 [n][k] ----------------
__global__ void prep_w_kernel(const float* __restrict__ W) {
    const int n = blockIdx.x;
    for (int k = threadIdx.x; k < K_TOT; k += blockDim.x)
        g_Wh[n * K_TOT + k] = __float2half_rn(W[(size_t)k * C_OUT + n]);
}

// ---------------- prep: build full fp16 patch [N][1280] ----------------
// 512 threads, 16 rows/CTA, 32 threads per row, each thread 8 channels.
__global__ void __launch_bounds__(512)
prep_patch_kernel(const float* __restrict__ x,
                  const int* __restrict__ idx1, const int* __restrict__ idx2,
                  const int* __restrict__ idx3, const int* __restrict__ idx4,
                  int nRows)
{
    const int row = blockIdx.x * 16 + (threadIdx.x >> 5);
    if (row >= nRows) return;
    const int c8 = (threadIdx.x & 31) * 8;

    const int ia = idx1[row], ib = idx2[row], ic = idx3[row], id = idx4[row];

    const float4 x0 = *(const float4*)(x + (size_t)row * C_IN + c8);
    const float4 x1 = *(const float4*)(x + (size_t)row * C_IN + c8 + 4);
    const float4 a0 = *(const float4*)(x + (size_t)ia * C_IN + c8);
    const float4 a1 = *(const float4*)(x + (size_t)ia * C_IN + c8 + 4);
    const float4 b0 = *(const float4*)(x + (size_t)ib * C_IN + c8);
    const float4 b1 = *(const float4*)(x + (size_t)ib * C_IN + c8 + 4);
    const float4 c0 = *(const float4*)(x + (size_t)ic * C_IN + c8);
    const float4 c1 = *(const float4*)(x + (size_t)ic * C_IN + c8 + 4);
    const float4 d0 = *(const float4*)(x + (size_t)id * C_IN + c8);
    const float4 d1 = *(const float4*)(x + (size_t)id * C_IN + c8 + 4);

    __half* pr = g_patch + (size_t)row * K_TOT;

    // seg0: x
    *(uint4*)(pr + 0*256 + c8) = make_uint4(pkh2(x0.x, x0.y), pkh2(x0.z, x0.w),
                                            pkh2(x1.x, x1.y), pkh2(x1.z, x1.w));
    // seg1: |a - c|
    *(uint4*)(pr + 1*256 + c8) = make_uint4(
        pkh2(fabsf(a0.x-c0.x), fabsf(a0.y-c0.y)), pkh2(fabsf(a0.z-c0.z), fabsf(a0.w-c0.w)),
        pkh2(fabsf(a1.x-c1.x), fabsf(a1.y-c1.y)), pkh2(fabsf(a1.z-c1.z), fabsf(a1.w-c1.w)));
    // seg2: a + c
    *(uint4*)(pr + 2*256 + c8) = make_uint4(
        pkh2(a0.x+c0.x, a0.y+c0.y), pkh2(a0.z+c0.z, a0.w+c0.w),
        pkh2(a1.x+c1.x, a1.y+c1.y), pkh2(a1.z+c1.z, a1.w+c1.w));
    // seg3: |b - d|
    *(uint4*)(pr + 3*256 + c8) = make_uint4(
        pkh2(fabsf(b0.x-d0.x), fabsf(b0.y-d0.y)), pkh2(fabsf(b0.z-d0.z), fabsf(b0.w-d0.w)),
        pkh2(fabsf(b1.x-d1.x), fabsf(b1.y-d1.y)), pkh2(fabsf(b1.z-d1.z), fabsf(b1.w-d1.w)));
    // seg4: b + d
    *(uint4*)(pr + 4*256 + c8) = make_uint4(
        pkh2(b0.x+d0.x, b0.y+d0.y), pkh2(b0.z+d0.z, b0.w+d0.w),
        pkh2(b1.x+d1.x, b1.y+d1.y), pkh2(b1.z+d1.z, b1.w+d1.w));
}

// ---------------- staging: pure cp.async for A (patch) and B (W) ----------------
__device__ __forceinline__ void stage_chunk(uint32_t sb, int kc, int tid,
                                            int bRow0, int nRows)
{
    const int b = kc & 1;
    const int kg0 = kc * KCH;
    const uint32_t As = sb + SO_A + b * 8192;
    const uint32_t Bs = sb + SO_B + b * 32768;

    // A: 64 rows x 64 fp16 = 512 x 16B, 2 iters of 256 threads
    #pragma unroll
    for (int it = 0; it < 2; ++it) {
        const int s = tid + it * NTHREADS;
        const int row = s >> 3;
        const int k8 = (s & 7) * 8;
        int rgc = bRow0 + row; if (rgc >= nRows) rgc = nRows - 1;
        cp_async16(As + swz(row * 128 + k8 * 2),
                   g_patch + (size_t)rgc * K_TOT + kg0 + k8);
    }

    // B: 256 rows x 64 fp16 = 2048 x 16B, 8 iters of 256 threads
    #pragma unroll
    for (int it = 0; it < 8; ++it) {
        const int s = tid + it * NTHREADS;
        const int n = s >> 3;
        const int k8 = (s & 7) * 8;
        cp_async16(Bs + swz(n * 128 + k8 * 2), g_Wh + n * K_TOT + kg0 + k8);
    }
}

// ---------------- main kernel ----------------
__global__ void __launch_bounds__(NTHREADS, 2)
smc_mma_kernel(const float* __restrict__ x,
               const float* __restrict__ bias, const float* __restrict__ gamma,
               const float* __restrict__ beta,
               float* __restrict__ out, int nRows)
{
    extern __shared__ char ds[];
    __shared__ float2 sPart[MT][4];

    const uint32_t sb = smem_u32(ds);
    const int tid  = threadIdx.x;
    const int lane = tid & 31;
    const int wid  = tid >> 5;
    const int wm   = wid & 1;     // warp row group (32 rows)
    const int wn   = wid >> 1;    // warp col group (64 cols)
    const int bRow0 = blockIdx.x * MT;

    float acc[2][8][4];
    #pragma unroll
    for (int i = 0; i < 2; i++)
        #pragma unroll
        for (int j = 0; j < 8; j++)
            #pragma unroll
            for (int e = 0; e < 4; e++) acc[i][j][e] = 0.f;

    // per-lane ldmatrix address components
    const int lA_row = wm * 32 + (lane & 7) + ((lane >> 3) & 1) * 8; // + mt*16
    const int lA_k8  = ((lane >> 4) & 1) * 8;
    const int lB_n   = wn * 64 + (lane & 7) + ((lane >> 4) & 1) * 8; // + ng*16
    const int lB_k8  = ((lane >> 3) & 1) * 8;

    stage_chunk(sb, 0, tid, bRow0, nRows);
    asm volatile("cp.async.wait_all;" ::: "memory");
    __syncthreads();

    for (int kc = 0; kc < NCH; ++kc) {
        if (kc + 1 < NCH)
            stage_chunk(sb, kc + 1, tid, bRow0, nRows);

        const uint32_t Ab = sb + SO_A + (kc & 1) * 8192;
        const uint32_t Bb = sb + SO_B + (kc & 1) * 32768;

        #pragma unroll
        for (int ks = 0; ks < 4; ++ks) {
            const int kb = ks * 16;
            uint32_t a0[4], a1[4];
            ldsm4(a0, Ab + swz((uint32_t)(lA_row        * 128 + (kb + lA_k8) * 2)));
            ldsm4(a1, Ab + swz((uint32_t)((lA_row + 16) * 128 + (kb + lA_k8) * 2)));
            #pragma unroll
            for (int ng = 0; ng < 4; ++ng) {
                const uint32_t boff = swz((uint32_t)((lB_n + ng * 16) * 128 + (kb + lB_k8) * 2));
                uint32_t bh[4];
                ldsm4(bh, Bb + boff);
                mma16816(acc[0][2*ng+0], a0, bh + 0);
                mma16816(acc[0][2*ng+1], a0, bh + 2);
                mma16816(acc[1][2*ng+0], a1, bh + 0);
                mma16816(acc[1][2*ng+1], a1, bh + 2);
            }
        }
        asm volatile("cp.async.wait_all;" ::: "memory");
        __syncthreads();
    }

    // ---------------- epilogue: bias + LN + residual + exact GELU ----------------
    const int cbase = wn * 64 + (lane & 3) * 2;

    #pragma unroll
    for (int nt = 0; nt < 8; ++nt) {
        const float2 bv = *(const float2*)(bias + cbase + nt * 8);
        #pragma unroll
        for (int mt = 0; mt < 2; ++mt) {
            acc[mt][nt][0] += bv.x; acc[mt][nt][1] += bv.y;
            acc[mt][nt][2] += bv.x; acc[mt][nt][3] += bv.y;
        }
    }

    #pragma unroll
    for (int mt = 0; mt < 2; ++mt)
        #pragma unroll
        for (int h = 0; h < 2; ++h) {
            float s = 0.f, s2 = 0.f;
            #pragma unroll
            for (int nt = 0; nt < 8; ++nt) {
                const float y0 = acc[mt][nt][h*2], y1 = acc[mt][nt][h*2+1];
                s += y0 + y1; s2 += y0*y0 + y1*y1;
            }
            s  += __shfl_xor_sync(0xffffffffu, s, 1);
            s2 += __shfl_xor_sync(0xffffffffu, s2, 1);
            s  += __shfl_xor_sync(0xffffffffu, s, 2);
            s2 += __shfl_xor_sync(0xffffffffu, s2, 2);
            if ((lane & 3) == 0) {
                const int row = wm * 32 + mt * 16 + h * 8 + (lane >> 2);
                sPart[row][wn] = make_float2(s, s2);
            }
        }
    __syncthreads();

    float2 gv[8], ev[8];
    #pragma unroll
    for (int nt = 0; nt < 8; ++nt) {
        gv[nt] = *(const float2*)(gamma + cbase + nt * 8);
        ev[nt] = *(const float2*)(beta  + cbase + nt * 8);
    }

    #pragma unroll
    for (int mt = 0; mt < 2; ++mt)
        #pragma unroll
        for (int h = 0; h < 2; ++h) {
            const int row = wm * 32 + mt * 16 + h * 8 + (lane >> 2);
            const float2 p0 = sPart[row][0], p1 = sPart[row][1];
            const float2 p2 = sPart[row][2], p3 = sPart[row][3];
            const float S  = p0.x + p1.x + p2.x + p3.x;
            const float S2 = p0.y + p1.y + p2.y + p3.y;
            const float mu = S * (1.0f / 256.0f);
            const float var = S2 * (1.0f / 256.0f) - mu * mu;
            const float rstd = rsqrtf(var + 1e-5f);
            const int rg = bRow0 + row;
            if (rg < nRows) {
                #pragma unroll
                for (int nt = 0; nt < 8; ++nt) {
                    const float2 xv = *(const float2*)(x + (size_t)rg * C_IN + cbase + nt * 8);
                    const float t0 = (acc[mt][nt][h*2]   - mu) * rstd * gv[nt].x + ev[nt].x + xv.x;
                    const float t1 = (acc[mt][nt][h*2+1] - mu) * rstd * gv[nt].y + ev[nt].y + xv.y;
                    *(float2*)(out + (size_t)rg * C_IN + cbase + nt * 8) =
                        make_float2(t0 * normcdff(t0), t1 * normcdff(t1));
                }
            }
        }
}

extern "C" void kernel_launch(void* const* d_in, const int* in_sizes, int n_in,
                              void* d_out, int out_size)
{
    const float* x     = (const float*)d_in[0];
    const int*   idx1  = (const int*)d_in[1];
    const int*   idx2  = (const int*)d_in[2];
    const int*   idx3  = (const int*)d_in[3];
    const int*   idx4  = (const int*)d_in[4];
    const float* W     = (const float*)d_in[5];
    const float* bias  = (const float*)d_in[6];
    const float* gamma = (const float*)d_in[7];
    const float* beta  = (const float*)d_in[8];
    float* out = (float*)d_out;

    const int n = in_sizes[1];
    const int grid = (n + MT - 1) / MT;

    cudaFuncSetAttribute(smc_mma_kernel,
                         cudaFuncAttributeMaxDynamicSharedMemorySize, SMEM_BYTES);

    prep_w_kernel<<<C_OUT, 256>>>(W);
    prep_patch_kernel<<<(n + 15) / 16, 512>>>(x, idx1, idx2, idx3, idx4, n);
    smc_mma_kernel<<<grid, NTHREADS, SMEM_BYTES>>>(x, bias, gamma, beta, out, n);
}